// round 7
// baseline (speedup 1.0000x reference)
#include <cuda_runtime.h>
#include <cuda_bf16.h>
#include <mma.h>
#include <math.h>
using namespace nvcuda;

#define BB 4
#define TT 4096
#define DD 1024
#define TOPR 256
#define RESTR (TT-TOPR)          // 3840
#define NSEG 32
#define SEGR (TOPR/NSEG)         // 8
#define LIVE_TH (-110.0f)
#define DONE_TH (-115.0f)
#define EPSF 1e-6f

// fallback SIMT tile params
#define FBM 128
#define FBN 128
#define FBK 8
#define FPAD 132

// ------------------- scratch -------------------
__device__ float g_buf[(size_t)BB*TT*DD];
__device__ float q_buf[(size_t)BB*TT*DD];
__device__ float wk_buf[(size_t)BB*TT*DD];
__device__ float v_buf[(size_t)BB*TT*DD];
__device__ float sc_buf[(size_t)BB*TT*TT];
__device__ float carry_buf[BB*DD];
__device__ int   s_min_g[BB];
__device__ int   band_done_g[BB];

// ===================== proj pair 1: q + k (tf32), shared A tile =====================
// grid (DD/64, TOPR/128, BB), block 256 (8 warps, 4x2 of 32x32)
__global__ void __launch_bounds__(256) k_proj_qk(const float* __restrict__ x,
        const float* __restrict__ Wq, const float* __restrict__ Wk,
        const float* __restrict__ bq, const float* __restrict__ bk)
{
    const int b = blockIdx.z;
    if (blockIdx.x == 0 && blockIdx.y == 0 && b == 0 && threadIdx.x < BB) {
        s_min_g[threadIdx.x] = TT; band_done_g[threadIdx.x] = 0;
    }
    const int m0 = RESTR + blockIdx.y * 128;
    const int n0 = blockIdx.x * 64;

    __shared__ __align__(32) char sb[36864];
    float (*Af)[36] = (float(*)[36])sb;                // 128x36 = 18432B
    float (*Bq)[36] = (float(*)[36])(sb + 18432);      // 64x36  =  9216B
    float (*Bk)[36] = (float(*)[36])(sb + 27648);      // 64x36
    float (*Obuf)[68] = (float(*)[68])sb;              // 128x68 = 34816B (after loop)

    wmma::fragment<wmma::accumulator,16,16,8,float> accQ[2][2], accK[2][2];
    #pragma unroll
    for (int i=0;i<2;i++)
        #pragma unroll
        for (int j=0;j<2;j++) { wmma::fill_fragment(accQ[i][j], 0.0f);
                                wmma::fill_fragment(accK[i][j], 0.0f); }

    const int tid = threadIdx.x, wid = tid >> 5;
    const int m_off = (wid >> 1) * 32, n_off = (wid & 1) * 32;
    const int ar = tid >> 1, ac = (tid & 1) * 16;
    const int br = tid >> 2, bc = (tid & 3) * 8;
    const float* Abase = x + ((size_t)b*TT + m0) * DD;

    for (int kt = 0; kt < DD; kt += 32) {
        float4 a0 = *(const float4*)&Abase[(size_t)ar*DD + kt + ac];
        float4 a1 = *(const float4*)&Abase[(size_t)ar*DD + kt + ac + 4];
        float4 a2 = *(const float4*)&Abase[(size_t)ar*DD + kt + ac + 8];
        float4 a3 = *(const float4*)&Abase[(size_t)ar*DD + kt + ac + 12];
        float4 q0 = *(const float4*)&Wq[(size_t)(n0 + br)*DD + kt + bc];
        float4 q1 = *(const float4*)&Wq[(size_t)(n0 + br)*DD + kt + bc + 4];
        float4 k0 = *(const float4*)&Wk[(size_t)(n0 + br)*DD + kt + bc];
        float4 k1 = *(const float4*)&Wk[(size_t)(n0 + br)*DD + kt + bc + 4];
        __syncthreads();
        {
            float av[16] = {a0.x,a0.y,a0.z,a0.w,a1.x,a1.y,a1.z,a1.w,
                            a2.x,a2.y,a2.z,a2.w,a3.x,a3.y,a3.z,a3.w};
            float qv[8]  = {q0.x,q0.y,q0.z,q0.w,q1.x,q1.y,q1.z,q1.w};
            float kv[8]  = {k0.x,k0.y,k0.z,k0.w,k1.x,k1.y,k1.z,k1.w};
            #pragma unroll
            for (int i = 0; i < 16; ++i) Af[ar][ac+i] = wmma::__float_to_tf32(av[i]);
            #pragma unroll
            for (int i = 0; i < 8; ++i) {
                Bq[br][bc+i] = wmma::__float_to_tf32(qv[i]);
                Bk[br][bc+i] = wmma::__float_to_tf32(kv[i]);
            }
        }
        __syncthreads();

        #pragma unroll
        for (int k8 = 0; k8 < 4; ++k8) {
            wmma::fragment<wmma::matrix_a,16,16,8,wmma::precision::tf32,wmma::row_major> ah[2];
            wmma::fragment<wmma::matrix_b,16,16,8,wmma::precision::tf32,wmma::col_major> bh[2], bh2[2];
            #pragma unroll
            for (int i=0;i<2;i++) wmma::load_matrix_sync(ah[i], &Af[m_off+i*16][k8*8], 36);
            #pragma unroll
            for (int j=0;j<2;j++) wmma::load_matrix_sync(bh[j], &Bq[n_off+j*16][k8*8], 36);
            #pragma unroll
            for (int j=0;j<2;j++) wmma::load_matrix_sync(bh2[j], &Bk[n_off+j*16][k8*8], 36);
            #pragma unroll
            for (int i=0;i<2;i++)
                #pragma unroll
                for (int j=0;j<2;j++) {
                    wmma::mma_sync(accQ[i][j], ah[i], bh[j],  accQ[i][j]);
                    wmma::mma_sync(accK[i][j], ah[i], bh2[j], accK[i][j]);
                }
        }
    }

    // epilogue: q then k, staged through Obuf
    #pragma unroll
    for (int mat = 0; mat < 2; ++mat) {
        __syncthreads();
        #pragma unroll
        for (int i=0;i<2;i++)
            #pragma unroll
            for (int j=0;j<2;j++) {
                if (mat == 0) wmma::store_matrix_sync(&Obuf[m_off+i*16][n_off+j*16], accQ[i][j], 68, wmma::mem_row_major);
                else          wmma::store_matrix_sync(&Obuf[m_off+i*16][n_off+j*16], accK[i][j], 68, wmma::mem_row_major);
            }
        __syncthreads();
        const float* bias = (mat == 0) ? bq : bk;
        float* dst = (mat == 0) ? q_buf : wk_buf;
        for (int e = tid; e < 128*16; e += 256) {
            const int r = e >> 4, c4 = (e & 15) * 4;
            float4 y = *(float4*)&Obuf[r][c4];
            float4 bb4 = *(const float4*)&bias[n0 + c4];
            y.x = fmaxf(y.x + bb4.x, 0.f); y.y = fmaxf(y.y + bb4.y, 0.f);
            y.z = fmaxf(y.z + bb4.z, 0.f); y.w = fmaxf(y.w + bb4.w, 0.f);
            *(float4*)&dst[((size_t)b*TT + m0 + r)*DD + n0 + c4] = y;
        }
    }
}

// ===================== proj pair 2: v + a (bf16 3-product split), shared A =====================
__global__ void __launch_bounds__(256) k_proj_va(const float* __restrict__ x,
        const float* __restrict__ Wv, const float* __restrict__ Wa,
        const float* __restrict__ bv, const float* __restrict__ ba)
{
    const int b = blockIdx.z;
    const int m0 = RESTR + blockIdx.y * 128;
    const int n0 = blockIdx.x * 64;

    __shared__ __align__(32) char sb[40960];
    __nv_bfloat16 (*Ahb)[40] = (__nv_bfloat16(*)[40])sb;            // 128x40x2 = 10240B
    __nv_bfloat16 (*Alb)[40] = (__nv_bfloat16(*)[40])(sb + 10240);
    __nv_bfloat16 (*Bvh)[40] = (__nv_bfloat16(*)[40])(sb + 20480); // 64x40x2 = 5120B
    __nv_bfloat16 (*Bvl)[40] = (__nv_bfloat16(*)[40])(sb + 25600);
    __nv_bfloat16 (*Bah)[40] = (__nv_bfloat16(*)[40])(sb + 30720);
    __nv_bfloat16 (*Bal)[40] = (__nv_bfloat16(*)[40])(sb + 35840);
    float (*Obuf)[68] = (float(*)[68])sb;

    wmma::fragment<wmma::accumulator,16,16,16,float> accV[2][2], accA[2][2];
    #pragma unroll
    for (int i=0;i<2;i++)
        #pragma unroll
        for (int j=0;j<2;j++) { wmma::fill_fragment(accV[i][j], 0.0f);
                                wmma::fill_fragment(accA[i][j], 0.0f); }

    const int tid = threadIdx.x, wid = tid >> 5;
    const int m_off = (wid >> 1) * 32, n_off = (wid & 1) * 32;
    const int ar = tid >> 1, ac = (tid & 1) * 16;
    const int br = tid >> 2, bc = (tid & 3) * 8;
    const float* Abase = x + ((size_t)b*TT + m0) * DD;

    for (int kt = 0; kt < DD; kt += 32) {
        float4 a0 = *(const float4*)&Abase[(size_t)ar*DD + kt + ac];
        float4 a1 = *(const float4*)&Abase[(size_t)ar*DD + kt + ac + 4];
        float4 a2 = *(const float4*)&Abase[(size_t)ar*DD + kt + ac + 8];
        float4 a3 = *(const float4*)&Abase[(size_t)ar*DD + kt + ac + 12];
        float4 v0 = *(const float4*)&Wv[(size_t)(n0 + br)*DD + kt + bc];
        float4 v1 = *(const float4*)&Wv[(size_t)(n0 + br)*DD + kt + bc + 4];
        float4 w0 = *(const float4*)&Wa[(size_t)(n0 + br)*DD + kt + bc];
        float4 w1 = *(const float4*)&Wa[(size_t)(n0 + br)*DD + kt + bc + 4];
        __syncthreads();
        {
            float av[16] = {a0.x,a0.y,a0.z,a0.w,a1.x,a1.y,a1.z,a1.w,
                            a2.x,a2.y,a2.z,a2.w,a3.x,a3.y,a3.z,a3.w};
            float vv[8]  = {v0.x,v0.y,v0.z,v0.w,v1.x,v1.y,v1.z,v1.w};
            float wv[8]  = {w0.x,w0.y,w0.z,w0.w,w1.x,w1.y,w1.z,w1.w};
            #pragma unroll
            for (int i = 0; i < 16; ++i) {
                __nv_bfloat16 h = __float2bfloat16_rn(av[i]);
                Ahb[ar][ac+i] = h;
                Alb[ar][ac+i] = __float2bfloat16_rn(av[i] - __bfloat162float(h));
            }
            #pragma unroll
            for (int i = 0; i < 8; ++i) {
                __nv_bfloat16 h = __float2bfloat16_rn(vv[i]);
                Bvh[br][bc+i] = h;
                Bvl[br][bc+i] = __float2bfloat16_rn(vv[i] - __bfloat162float(h));
                __nv_bfloat16 h2 = __float2bfloat16_rn(wv[i]);
                Bah[br][bc+i] = h2;
                Bal[br][bc+i] = __float2bfloat16_rn(wv[i] - __bfloat162float(h2));
            }
        }
        __syncthreads();

        #pragma unroll
        for (int k16 = 0; k16 < 2; ++k16) {
            wmma::fragment<wmma::matrix_a,16,16,16,__nv_bfloat16,wmma::row_major> ah[2], al[2];
            #pragma unroll
            for (int i=0;i<2;i++) {
                wmma::load_matrix_sync(ah[i], &Ahb[m_off+i*16][k16*16], 40);
                wmma::load_matrix_sync(al[i], &Alb[m_off+i*16][k16*16], 40);
            }
            {   // v
                wmma::fragment<wmma::matrix_b,16,16,16,__nv_bfloat16,wmma::col_major> bh[2], bl[2];
                #pragma unroll
                for (int j=0;j<2;j++) {
                    wmma::load_matrix_sync(bh[j], &Bvh[n_off+j*16][k16*16], 40);
                    wmma::load_matrix_sync(bl[j], &Bvl[n_off+j*16][k16*16], 40);
                }
                #pragma unroll
                for (int i=0;i<2;i++)
                    #pragma unroll
                    for (int j=0;j<2;j++) {
                        wmma::mma_sync(accV[i][j], ah[i], bh[j], accV[i][j]);
                        wmma::mma_sync(accV[i][j], ah[i], bl[j], accV[i][j]);
                        wmma::mma_sync(accV[i][j], al[i], bh[j], accV[i][j]);
                    }
            }
            {   // a
                wmma::fragment<wmma::matrix_b,16,16,16,__nv_bfloat16,wmma::col_major> bh[2], bl[2];
                #pragma unroll
                for (int j=0;j<2;j++) {
                    wmma::load_matrix_sync(bh[j], &Bah[n_off+j*16][k16*16], 40);
                    wmma::load_matrix_sync(bl[j], &Bal[n_off+j*16][k16*16], 40);
                }
                #pragma unroll
                for (int i=0;i<2;i++)
                    #pragma unroll
                    for (int j=0;j<2;j++) {
                        wmma::mma_sync(accA[i][j], ah[i], bh[j], accA[i][j]);
                        wmma::mma_sync(accA[i][j], ah[i], bl[j], accA[i][j]);
                        wmma::mma_sync(accA[i][j], al[i], bh[j], accA[i][j]);
                    }
            }
        }
    }

    // epilogue: v then a, staged through Obuf
    #pragma unroll
    for (int mat = 0; mat < 2; ++mat) {
        __syncthreads();
        #pragma unroll
        for (int i=0;i<2;i++)
            #pragma unroll
            for (int j=0;j<2;j++) {
                if (mat == 0) wmma::store_matrix_sync(&Obuf[m_off+i*16][n_off+j*16], accV[i][j], 68, wmma::mem_row_major);
                else          wmma::store_matrix_sync(&Obuf[m_off+i*16][n_off+j*16], accA[i][j], 68, wmma::mem_row_major);
            }
        __syncthreads();
        const float* bias = (mat == 0) ? bv : ba;
        for (int e = tid; e < 128*16; e += 256) {
            const int r = e >> 4, c4 = (e & 15) * 4;
            float4 y = *(float4*)&Obuf[r][c4];
            float4 bb4 = *(const float4*)&bias[n0 + c4];
            y.x += bb4.x; y.y += bb4.y; y.z += bb4.z; y.w += bb4.w;
            const size_t idx = ((size_t)b*TT + m0 + r)*DD + n0 + c4;
            if (mat == 0) {
                *(float4*)&v_buf[idx] = y;
            } else {
                y.x = __logf(1.0f/(1.0f + __expf(-y.x)) + 1e-6f);
                y.y = __logf(1.0f/(1.0f + __expf(-y.y)) + 1e-6f);
                y.z = __logf(1.0f/(1.0f + __expf(-y.z)) + 1e-6f);
                y.w = __logf(1.0f/(1.0f + __expf(-y.w)) + 1e-6f);
                *(float4*)&g_buf[idx] = y;
            }
        }
    }
}

// ===================== fused segmented reverse scan of top chunk =====================
// grid (NSEG, BB), block 256. Each block: suffix offset from raw g rows above its
// segment (L2-resident), local 8-row scan + wk gating + liveness. seg==0 block's
// final g is the full column total -> carry + band_done.
__global__ void k_scan_all()
{
    const int seg = blockIdx.x, b = blockIdx.y, tid = threadIdx.x;
    const float4* gb = (const float4*)g_buf;
    float4 g = make_float4(0.f,0.f,0.f,0.f);
    #pragma unroll 4
    for (int t = RESTR + (seg + 1) * SEGR; t < TT; ++t) {
        float4 v = gb[((size_t)b*TT + t)*256 + tid];
        g.x += v.x; g.y += v.y; g.z += v.z; g.w += v.w;
    }

    float4* wb = (float4*)wk_buf;
    const int t0 = RESTR + seg * SEGR;
    int live = TT;
    #pragma unroll
    for (int r = SEGR - 1; r >= 0; --r) {
        size_t o = ((size_t)b*TT + t0 + r)*256 + tid;
        float4 la = gb[o];
        g.x += la.x; g.y += la.y; g.z += la.z; g.w += la.w;
        float4 w = wb[o];
        w.x *= __expf(g.x); w.y *= __expf(g.y);
        w.z *= __expf(g.z); w.w *= __expf(g.w);
        wb[o] = w;
        float m = fmaxf(fmaxf(g.x, g.y), fmaxf(g.z, g.w));
        if (m >= LIVE_TH) live = t0 + r;
    }

    __shared__ int slive;
    if (tid == 0) slive = TT;
    __syncthreads();
    atomicMin(&slive, live);

    if (seg == 0) {
        ((float4*)carry_buf)[b*256 + tid] = g;
        __shared__ float smax[256];
        smax[tid] = fmaxf(fmaxf(g.x, g.y), fmaxf(g.z, g.w));
        __syncthreads();
        for (int s = 128; s > 0; s >>= 1) {
            if (tid < s) smax[tid] = fmaxf(smax[tid], smax[tid + s]);
            __syncthreads();
        }
        if (tid == 0) band_done_g[b] = (smax[0] < DONE_TH) ? 1 : 0;
    } else {
        __syncthreads();
    }
    if (tid == 0 && slive < TT) atomicMin(&s_min_g[b], slive);
}

// ===================== SIMT fallback core (normally dead) =====================
template<int BT>
__device__ __forceinline__ void gemm_tile(const float* __restrict__ A, int lda,
                                          const float* __restrict__ B, int ldb,
                                          int m0, int n0, int k0, int k1,
                                          float (&acc)[8][8],
                                          float (*As)[FPAD], float (*Bs)[FPAD])
{
    const int tid  = threadIdx.x;
    const int tx   = tid & 15;
    const int ty   = tid >> 4;
    const int lrow = tid >> 1;
    const int lkq  = (tid & 1) * 4;

    for (int kt = k0; kt < k1; kt += FBK) {
        float4 av = *(const float4*)&A[(size_t)(m0 + lrow) * lda + kt + lkq];
        float4 bv = *(const float4*)&B[(size_t)(n0 + lrow) * ldb + kt + lkq];
        __syncthreads();
        As[lkq+0][lrow] = av.x; As[lkq+1][lrow] = av.y;
        As[lkq+2][lrow] = av.z; As[lkq+3][lrow] = av.w;
        Bs[lkq+0][lrow] = bv.x; Bs[lkq+1][lrow] = bv.y;
        Bs[lkq+2][lrow] = bv.z; Bs[lkq+3][lrow] = bv.w;
        __syncthreads();
        #pragma unroll
        for (int kk = 0; kk < FBK; ++kk) {
            float a[8], bb[8];
            *(float4*)(a)    = *(const float4*)&As[kk][ty*8];
            *(float4*)(a+4)  = *(const float4*)&As[kk][ty*8+4];
            *(float4*)(bb)   = *(const float4*)&Bs[kk][tx*8];
            *(float4*)(bb+4) = *(const float4*)&Bs[kk][tx*8+4];
            #pragma unroll
            for (int i = 0; i < 8; ++i)
                #pragma unroll
                for (int j = 0; j < 8; ++j)
                    acc[i][j] += a[i] * bb[j];
        }
    }
}

__global__ void __launch_bounds__(256) k_loga_rest(const float* __restrict__ x,
                       const float* __restrict__ Wa, const float* __restrict__ ba)
{
    const int b = blockIdx.z;
    if (band_done_g[b]) return;
    __shared__ float As[FBK][FPAD];
    __shared__ float Bs[FBK][FPAD];
    const int t0 = blockIdx.y*FBM;
    const int n0 = blockIdx.x*FBN;
    float acc[8][8];
    #pragma unroll
    for (int i=0;i<8;i++)
        #pragma unroll
        for (int j=0;j<8;j++) acc[i][j]=0.f;
    gemm_tile<1>(x + (size_t)b*TT*DD, DD, Wa, DD, t0, n0, 0, DD, acc, As, Bs);

    const int tx = threadIdx.x & 15, ty = threadIdx.x >> 4;
    float* gb = g_buf + (size_t)b*TT*DD;
    #pragma unroll
    for (int i = 0; i < 8; ++i) {
        const int t = t0 + ty*8 + i;
        #pragma unroll
        for (int j = 0; j < 8; ++j) {
            const int n = n0 + tx*8 + j;
            float y = acc[i][j] + ba[n];
            float s = 1.0f / (1.0f + __expf(-y));
            gb[(size_t)t*DD + n] = __logf(s + 1e-6f);
        }
    }
}

__global__ void k_scan_rest()
{
    const int b = blockIdx.x;
    if (band_done_g[b]) return;
    const int tid = threadIdx.x;
    float4* gb = (float4*)(g_buf + (size_t)b*TT*DD);
    float4 g = ((float4*)carry_buf)[b*256 + tid];
    int live = TT;
    #pragma unroll 8
    for (int t = RESTR - 1; t >= 0; --t) {
        float4 la = gb[(size_t)t*256 + tid];
        g.x += la.x; g.y += la.y; g.z += la.z; g.w += la.w;
        gb[(size_t)t*256 + tid] = g;
        float m = fmaxf(fmaxf(g.x, g.y), fmaxf(g.z, g.w));
        if (m >= LIVE_TH) live = t;
    }
    ((float4*)carry_buf)[b*256 + tid] = g;

    __shared__ int slive;
    if (tid == 0) slive = TT;
    __syncthreads();
    atomicMin(&slive, live);
    __syncthreads();
    if (tid == 0 && slive < TT) atomicMin(&s_min_g[b], slive);
}

__global__ void __launch_bounds__(256) k_qkv_rest(const float* __restrict__ x,
                      const float* __restrict__ Wq, const float* __restrict__ bq,
                      const float* __restrict__ Wk, const float* __restrict__ bk,
                      const float* __restrict__ Wv, const float* __restrict__ bv)
{
    const int z = blockIdx.z, b = z / 3, mat = z % 3;
    const int smin = s_min_g[b];
    const int t0 = blockIdx.y * FBM;          // rows < RESTR only
    if (t0 + FBM <= smin) return;
    const float* W; const float* bias;
    if (mat == 0)      { W = Wq; bias = bq; }
    else if (mat == 1) { W = Wk; bias = bk; }
    else               { W = Wv; bias = bv; }

    __shared__ float As[FBK][FPAD];
    __shared__ float Bs[FBK][FPAD];
    const int n0 = blockIdx.x * FBN;
    float acc[8][8];
    #pragma unroll
    for (int i=0;i<8;i++)
        #pragma unroll
        for (int j=0;j<8;j++) acc[i][j]=0.f;
    gemm_tile<1>(x + (size_t)b*TT*DD, DD, W, DD, t0, n0, 0, DD, acc, As, Bs);

    const int tx = threadIdx.x & 15, ty = threadIdx.x >> 4;
    const size_t base = (size_t)b*TT*DD;
    #pragma unroll
    for (int i = 0; i < 8; ++i) {
        const int t = t0 + ty*8 + i;
        #pragma unroll
        for (int j = 0; j < 8; ++j) {
            const int n = n0 + tx*8 + j;
            float y = acc[i][j] + bias[n];
            size_t idx = base + (size_t)t*DD + n;
            if (mat == 0) {
                q_buf[idx] = fmaxf(y, 0.f);
            } else if (mat == 1) {
                float w = 0.f;
                if (t >= smin) w = fmaxf(y, 0.f) * __expf(g_buf[idx]);
                wk_buf[idx] = w;
            } else {
                v_buf[idx] = y;
            }
        }
    }
}

// ===================== wmma scores: sc = mask(q @ wk^T) =====================
__global__ void __launch_bounds__(256) k_scores()
{
    const int b = blockIdx.z;
    const int smin = s_min_g[b];
    const int t0 = blockIdx.y * 128;
    const int s0 = blockIdx.x * 64;
    if (t0 + 128 <= smin) return;
    if (s0 + 64 <= smin) return;
    if (s0 > t0 + 127) return;

    __shared__ __align__(32) float Ah[128][24], Bh[64][24];
    wmma::fragment<wmma::accumulator,16,16,8,float> acc[2][2];
    #pragma unroll
    for (int i=0;i<2;i++)
        #pragma unroll
        for (int j=0;j<2;j++) wmma::fill_fragment(acc[i][j], 0.0f);

    const int tid = threadIdx.x, wid = tid >> 5;
    const int m_off = (wid >> 1) * 32, n_off = (wid & 1) * 32;
    const int arow = tid >> 1, ac8 = (tid & 1) * 8;
    const float* Abase = q_buf + ((size_t)b*TT + t0) * DD;
    const float* Bbase = wk_buf + ((size_t)b*TT + s0) * DD;

    for (int kt = 0; kt < DD; kt += 16) {
        float4 a0 = *(const float4*)&Abase[(size_t)arow*DD + kt + ac8];
        float4 a1 = *(const float4*)&Abase[(size_t)arow*DD + kt + ac8 + 4];
        float4 b0, b1;
        if (tid < 128) {
            b0 = *(const float4*)&Bbase[(size_t)arow*DD + kt + ac8];
            b1 = *(const float4*)&Bbase[(size_t)arow*DD + kt + ac8 + 4];
        }
        __syncthreads();
        {
            float av[8] = {a0.x,a0.y,a0.z,a0.w,a1.x,a1.y,a1.z,a1.w};
            #pragma unroll
            for (int i = 0; i < 8; ++i) Ah[arow][ac8+i] = wmma::__float_to_tf32(av[i]);
            if (tid < 128) {
                float bv[8] = {b0.x,b0.y,b0.z,b0.w,b1.x,b1.y,b1.z,b1.w};
                #pragma unroll
                for (int i = 0; i < 8; ++i) Bh[arow][ac8+i] = wmma::__float_to_tf32(bv[i]);
            }
        }
        __syncthreads();
        #pragma unroll
        for (int k8 = 0; k8 < 2; ++k8) {
            wmma::fragment<wmma::matrix_a,16,16,8,wmma::precision::tf32,wmma::row_major> ah[2];
            wmma::fragment<wmma::matrix_b,16,16,8,wmma::precision::tf32,wmma::col_major> bh[2];
            #pragma unroll
            for (int i=0;i<2;i++) wmma::load_matrix_sync(ah[i], &Ah[m_off+i*16][k8*8], 24);
            #pragma unroll
            for (int j=0;j<2;j++) wmma::load_matrix_sync(bh[j], &Bh[n_off+j*16][k8*8], 24);
            #pragma unroll
            for (int i=0;i<2;i++)
                #pragma unroll
                for (int j=0;j<2;j++) wmma::mma_sync(acc[i][j], ah[i], bh[j], acc[i][j]);
        }
    }

    float* sc = sc_buf + (size_t)b*TT*TT;
    #pragma unroll
    for (int i=0;i<2;i++)
        #pragma unroll
        for (int j=0;j<2;j++)
            wmma::store_matrix_sync(&sc[(size_t)(t0 + m_off + i*16)*TT + s0 + n_off + j*16],
                                    acc[i][j], TT, wmma::mem_row_major);
    if (s0 + 63 > t0) {
        __syncthreads();
        for (int e = tid; e < 128*64; e += 256) {
            int r = e >> 6, c = e & 63;
            if (s0 + c > t0 + r) sc[(size_t)(t0 + r)*TT + s0 + c] = 0.f;
        }
    }
}

// ===================== wmma out: out = (sc @ v)/rowsum, denom fused from A loads =====
__global__ void __launch_bounds__(256) k_out(float* __restrict__ out)
{
    const int b = blockIdx.z;
    const int smin = s_min_g[b];
    const int t0 = blockIdx.y * 128;
    const int n0 = blockIdx.x * 64;
    const int tid = threadIdx.x;
    float* ob = out + (size_t)b*TT*DD;

    if (t0 + 128 <= smin) {
        float4 z = make_float4(0.f,0.f,0.f,0.f);
        for (int q = tid; q < 128*16; q += 256) {
            int r = q >> 4, c4 = q & 15;
            *(float4*)&ob[(size_t)(t0 + r)*DD + n0 + c4*4] = z;
        }
        return;
    }

    const int k0 = smin & ~63;
    const int k1 = t0 + 128;

    __shared__ __align__(32) float Ah[128][24], Bh[16][72];
    __shared__ __align__(16) float Obuf[128][68];
    __shared__ float sden[128];
    wmma::fragment<wmma::accumulator,16,16,8,float> acc[2][2];
    #pragma unroll
    for (int i=0;i<2;i++)
        #pragma unroll
        for (int j=0;j<2;j++) wmma::fill_fragment(acc[i][j], 0.0f);

    const int wid = tid >> 5;
    const int m_off = (wid >> 1) * 32, n_off = (wid & 1) * 32;
    const int arow = tid >> 1, ac8 = (tid & 1) * 8;
    const int brow = tid >> 4, bc4 = (tid & 15) * 4;
    const float* Abase = sc_buf + ((size_t)b*TT + t0) * TT;
    const float* Bbase = v_buf + (size_t)b*TT*DD;

    float dsum = 0.f;

    for (int kt = k0; kt < k1; kt += 16) {
        float4 a0 = *(const float4*)&Abase[(size_t)arow*TT + kt + ac8];
        float4 a1 = *(const float4*)&Abase[(size_t)arow*TT + kt + ac8 + 4];
        float4 bv = *(const float4*)&Bbase[(size_t)(kt + brow)*DD + n0 + bc4];
        dsum += a0.x + a0.y + a0.z + a0.w + a1.x + a1.y + a1.z + a1.w;
        __syncthreads();
        {
            float av[8] = {a0.x,a0.y,a0.z,a0.w,a1.x,a1.y,a1.z,a1.w};
            #pragma unroll
            for (int i = 0; i < 8; ++i) Ah[arow][ac8+i] = wmma::__float_to_tf32(av[i]);
            Bh[brow][bc4+0] = wmma::__float_to_tf32(bv.x);
            Bh[brow][bc4+1] = wmma::__float_to_tf32(bv.y);
            Bh[brow][bc4+2] = wmma::__float_to_tf32(bv.z);
            Bh[brow][bc4+3] = wmma::__float_to_tf32(bv.w);
        }
        __syncthreads();
        #pragma unroll
        for (int k8 = 0; k8 < 2; ++k8) {
            wmma::fragment<wmma::matrix_a,16,16,8,wmma::precision::tf32,wmma::row_major> ah[2];
            wmma::fragment<wmma::matrix_b,16,16,8,wmma::precision::tf32,wmma::row_major> bh[2];
            #pragma unroll
            for (int i=0;i<2;i++) wmma::load_matrix_sync(ah[i], &Ah[m_off+i*16][k8*8], 24);
            #pragma unroll
            for (int j=0;j<2;j++) wmma::load_matrix_sync(bh[j], &Bh[k8*8][n_off+j*16], 72);
            #pragma unroll
            for (int i=0;i<2;i++)
                #pragma unroll
                for (int j=0;j<2;j++) wmma::mma_sync(acc[i][j], ah[i], bh[j], acc[i][j]);
        }
    }

    dsum += __shfl_xor_sync(0xffffffffu, dsum, 1);
    if ((tid & 1) == 0) sden[arow] = dsum + EPSF;

    #pragma unroll
    for (int i=0;i<2;i++)
        #pragma unroll
        for (int j=0;j<2;j++)
            wmma::store_matrix_sync(&Obuf[m_off + i*16][n_off + j*16], acc[i][j],
                                    68, wmma::mem_row_major);
    __syncthreads();
    for (int q = tid; q < 128*16; q += 256) {
        int r = q >> 4, c4 = (q & 15) * 4;
        int t = t0 + r;
        float inv = (t >= smin) ? 1.0f / sden[r] : 0.0f;
        float4 vv = *(float4*)&Obuf[r][c4];
        vv.x *= inv; vv.y *= inv; vv.z *= inv; vv.w *= inv;
        *(float4*)&ob[(size_t)t*DD + n0 + c4] = vv;
    }
}

// ------------------- launch -------------------
extern "C" void kernel_launch(void* const* d_in, const int* in_sizes, int n_in,
                              void* d_out, int out_size)
{
    const float* x  = (const float*)d_in[0];
    const float* Wq = (const float*)d_in[1];
    const float* bq = (const float*)d_in[2];
    const float* Wk = (const float*)d_in[3];
    const float* bk = (const float*)d_in[4];
    const float* Wv = (const float*)d_in[5];
    const float* bv = (const float*)d_in[6];
    const float* Wa = (const float*)d_in[7];
    const float* ba = (const float*)d_in[8];
    float* out = (float*)d_out;

    // fast path: top 256 rows, paired projections sharing A
    k_proj_qk<<<dim3(DD/64, TOPR/128, BB), 256>>>(x, Wq, Wk, bq, bk);
    k_proj_va<<<dim3(DD/64, TOPR/128, BB), 256>>>(x, Wv, Wa, bv, ba);
    k_scan_all<<<dim3(NSEG, BB), 256>>>();

    // fallback for band extending below top chunk (normally dead)
    k_loga_rest<<<dim3(DD/FBN, RESTR/FBM, BB), 256>>>(x, Wa, ba);
    k_scan_rest<<<BB, 256>>>();
    k_qkv_rest<<<dim3(DD/FBN, RESTR/FBM, BB*3), 256>>>(x, Wq, bq, Wk, bk, Wv, bv);

    k_scores<<<dim3(TT/64, TT/128, BB), 256>>>();
    k_out<<<dim3(DD/64, TT/128, BB), 256>>>(out);
}